// round 2
// baseline (speedup 1.0000x reference)
#include <cuda_runtime.h>
#include <math.h>

#define B_    16
#define C_    64
#define H_    160
#define W_    160
#define OUT_  64
#define KEXP  4
#define HID   17
#define TEMPR 34.0f
#define HW    (H_*W_)

#define TILE  32
#define CHK   8
#define OCB   8

// Scratch (device globals: no allocation allowed in kernel_launch)
__device__ float g_pooled[B_*C_];
__device__ float g_attn[B_*KEXP];
__device__ float g_aggb[B_*OUT_];
__device__ float g_aggw[B_*OUT_*C_*9];

// ---------- Blackwell packed f32x2 helpers ----------
__device__ __forceinline__ void ffma2(unsigned long long& d,
                                      unsigned long long a,
                                      unsigned long long b) {
    asm("fma.rn.f32x2 %0, %1, %2, %0;" : "+l"(d) : "l"(a), "l"(b));
}
__device__ __forceinline__ unsigned long long dup2(float v) {
    unsigned long long r;
    asm("mov.b64 %0, {%1, %1};" : "=l"(r) : "f"(v));
    return r;
}
__device__ __forceinline__ void unpack2(unsigned long long v, float& lo, float& hi) {
    asm("mov.b64 {%0, %1}, %2;" : "=f"(lo), "=f"(hi) : "l"(v));
}

// ---------- 1. global average pool: pooled[b,c] ----------
__global__ void pool_kernel(const float* __restrict__ x) {
    int bc = blockIdx.x;                       // 0..1023
    const float4* p = (const float4*)(x + (size_t)bc * HW);
    float s = 0.f;
    for (int i = threadIdx.x; i < HW/4; i += blockDim.x) {
        float4 v = p[i];
        s += (v.x + v.y) + (v.z + v.w);
    }
    #pragma unroll
    for (int o = 16; o; o >>= 1) s += __shfl_xor_sync(0xffffffffu, s, o);
    __shared__ float red[8];
    if ((threadIdx.x & 31) == 0) red[threadIdx.x >> 5] = s;
    __syncthreads();
    if (threadIdx.x == 0) {
        float t = 0.f;
        #pragma unroll
        for (int i = 0; i < 8; i++) t += red[i];
        g_pooled[bc] = t * (1.0f / (float)HW);
    }
}

// ---------- 2. attention MLP + softmax + agg bias ----------
__global__ void attn_kernel(const float* __restrict__ fc1,
                            const float* __restrict__ fc2,
                            const float* __restrict__ bias_p) {
    int b = threadIdx.x;
    if (b >= B_) return;
    float pooled[C_];
    #pragma unroll
    for (int c = 0; c < C_; c++) pooled[c] = g_pooled[b*C_ + c];
    float hid[HID];
    for (int j = 0; j < HID; j++) {
        float s = 0.f;
        #pragma unroll
        for (int c = 0; c < C_; c++) s += pooled[c] * fc1[j*C_ + c];
        hid[j] = fmaxf(s, 0.f);
    }
    float lg[KEXP];
    for (int k = 0; k < KEXP; k++) {
        float s = 0.f;
        #pragma unroll
        for (int j = 0; j < HID; j++) s += hid[j] * fc2[k*HID + j];
        lg[k] = s * (1.0f / TEMPR);
    }
    float m = fmaxf(fmaxf(lg[0], lg[1]), fmaxf(lg[2], lg[3]));
    float e[KEXP], sum = 0.f;
    for (int k = 0; k < KEXP; k++) { e[k] = expf(lg[k] - m); sum += e[k]; }
    float a[KEXP];
    for (int k = 0; k < KEXP; k++) { a[k] = e[k] / sum; g_attn[b*KEXP + k] = a[k]; }
    for (int o = 0; o < OUT_; o++) {
        float s = 0.f;
        #pragma unroll
        for (int k = 0; k < KEXP; k++) s += a[k] * bias_p[k*OUT_ + o];
        g_aggb[b*OUT_ + o] = s;
    }
}

// ---------- 3. aggregate weights: aggw[b,o,c,ij] = sum_k attn[b,k]*weight[k,o,c,ij] ----------
__global__ void aggw_kernel(const float* __restrict__ weight) {
    int idx = blockIdx.x * blockDim.x + threadIdx.x;
    const int R = OUT_*C_*9;                    // 36864
    if (idx >= B_*R) return;
    int b = idx / R;
    int r = idx - b*R;
    float s = 0.f;
    #pragma unroll
    for (int k = 0; k < KEXP; k++)
        s += g_attn[b*KEXP + k] * weight[(size_t)k*R + r];
    g_aggw[idx] = s;
}

// ---------- 4. per-batch 3x3 conv (dynamic weights), packed f32x2 ----------
__global__ __launch_bounds__(256)
void conv_kernel(const float* __restrict__ x, float* __restrict__ out) {
    __shared__ float xs[CHK][34][35];          // padded row stride (bank spread)
    __shared__ float ws[CHK][9][OCB];          // oc contiguous -> natural pairs

    int bz  = blockIdx.z;
    int b   = bz >> 3;
    int og  = bz & 7;
    int ty0 = blockIdx.y * TILE;
    int tx0 = blockIdx.x * TILE;
    int tid = threadIdx.x;
    int tx  = tid & 15;                        // 16 x-positions (2 px each)
    int ty  = tid >> 4;                        // 16 y-positions (2 px each)

    // acc[pixel 0..3 (row*2+col)][oc-pair 0..3], each f32x2 = (oc_even, oc_odd)
    unsigned long long acc[4][4];
    #pragma unroll
    for (int i = 0; i < 4; i++)
        #pragma unroll
        for (int j = 0; j < 4; j++) acc[i][j] = 0ull;

    const float* xb = x + (size_t)b * C_ * HW;

    for (int cc = 0; cc < C_; cc += CHK) {
        // stage x chunk (with halo, zero-padded)
        for (int i = tid; i < CHK*34*34; i += 256) {
            int c  = i / (34*34);
            int r  = i - c*(34*34);
            int yy = r / 34;
            int xx = r - yy*34;
            int gy = ty0 + yy - 1;
            int gx = tx0 + xx - 1;
            float v = 0.f;
            if (gy >= 0 && gy < H_ && gx >= 0 && gx < W_)
                v = __ldg(xb + (size_t)(cc + c)*HW + gy*W_ + gx);
            xs[c][yy][xx] = v;
        }
        // stage weight chunk
        for (int i = tid; i < CHK*9*OCB; i += 256) {
            int c  = i / 72;
            int r  = i - c*72;
            int ij = r / OCB;
            int oc = r - ij*OCB;
            ws[c][ij][oc] =
                g_aggw[(((b*OUT_) + og*OCB + oc)*C_ + cc + c)*9 + ij];
        }
        __syncthreads();

        #pragma unroll 2
        for (int c = 0; c < CHK; ++c) {
            #pragma unroll
            for (int ki = 0; ki < 3; ++ki) {
                #pragma unroll
                for (int kj = 0; kj < 3; ++kj) {
                    const float* xr = &xs[c][ty*2 + ki][tx*2 + kj];
                    unsigned long long xd0 = dup2(xr[0]);
                    unsigned long long xd1 = dup2(xr[1]);
                    unsigned long long xd2 = dup2(xr[35]);
                    unsigned long long xd3 = dup2(xr[36]);
                    const unsigned long long* wq =
                        (const unsigned long long*)&ws[c][ki*3 + kj][0];
                    unsigned long long w0 = wq[0], w1 = wq[1],
                                       w2 = wq[2], w3 = wq[3];
                    ffma2(acc[0][0], xd0, w0); ffma2(acc[0][1], xd0, w1);
                    ffma2(acc[0][2], xd0, w2); ffma2(acc[0][3], xd0, w3);
                    ffma2(acc[1][0], xd1, w0); ffma2(acc[1][1], xd1, w1);
                    ffma2(acc[1][2], xd1, w2); ffma2(acc[1][3], xd1, w3);
                    ffma2(acc[2][0], xd2, w0); ffma2(acc[2][1], xd2, w1);
                    ffma2(acc[2][2], xd2, w2); ffma2(acc[2][3], xd2, w3);
                    ffma2(acc[3][0], xd3, w0); ffma2(acc[3][1], xd3, w1);
                    ffma2(acc[3][2], xd3, w2); ffma2(acc[3][3], xd3, w3);
                }
            }
        }
        __syncthreads();
    }

    // epilogue: unpack, add bias, coalesced float2 stores
    int py = ty0 + ty*2;
    int px = tx0 + tx*2;
    #pragma unroll
    for (int oc2 = 0; oc2 < 4; ++oc2) {
        float2 bias2 = *(const float2*)&g_aggb[b*OUT_ + og*OCB + oc2*2];
        #pragma unroll
        for (int row = 0; row < 2; ++row) {
            float lo0, hi0, lo1, hi1;
            unpack2(acc[row*2 + 0][oc2], lo0, hi0);   // pixel (row, 0)
            unpack2(acc[row*2 + 1][oc2], lo1, hi1);   // pixel (row, 1)
            float* o0 = out + (((size_t)b*OUT_ + og*OCB + oc2*2)*H_ + (py + row))*W_ + px;
            float* o1 = o0 + (size_t)HW;
            *(float2*)o0 = make_float2(lo0 + bias2.x, lo1 + bias2.x);
            *(float2*)o1 = make_float2(hi0 + bias2.y, hi1 + bias2.y);
        }
    }
}

extern "C" void kernel_launch(void* const* d_in, const int* in_sizes, int n_in,
                              void* d_out, int out_size) {
    const float* x      = (const float*)d_in[0];
    const float* fc1    = (const float*)d_in[1];
    const float* fc2    = (const float*)d_in[2];
    const float* weight = (const float*)d_in[3];
    const float* bias_p = (const float*)d_in[4];
    float* out = (float*)d_out;

    pool_kernel<<<B_*C_, 256>>>(x);
    attn_kernel<<<1, 32>>>(fc1, fc2, bias_p);
    aggw_kernel<<<(B_*OUT_*C_*9 + 255)/256, 256>>>(weight);
    dim3 grid(W_/TILE, H_/TILE, B_*(OUT_/OCB));
    conv_kernel<<<grid, 256>>>(x, out);
}